// round 4
// baseline (speedup 1.0000x reference)
#include <cuda_runtime.h>

#define B_DIM 1024
#define T_DIM 256
#define D_DIM 64
#define H_DIM 128
#define GH 256          // 2H
#define XCOLS 384       // 256 gate cols + 128 cand cols
#define RROWS 4
#define NGROUPS (B_DIM / RROWS)   // 256
#define KPAD 132        // padded k-stride (floats): 132 mod 32 = 4 -> conflict-free LDS.128

// Scratch (device globals: no allocation allowed).
static __device__ float g_Xbuf[(size_t)B_DIM * T_DIM * XCOLS]; // ~402 MB
static __device__ int   g_perm[B_DIM];
static __device__ int   g_counter;

typedef unsigned long long ull;

__device__ __forceinline__ float fast_sigmoid(float z) {
    return __fdividef(1.0f, 1.0f + __expf(-z));
}
__device__ __forceinline__ float fast_tanh(float z) {
    return 1.0f - __fdividef(2.0f, __expf(2.0f * z) + 1.0f);
}

// packed fp32x2 helpers (Blackwell FFMA2 — PTX-only, exact fp32)
__device__ __forceinline__ void ffma2(ull& acc, ull a, ull b) {
    asm("fma.rn.f32x2 %0, %1, %2, %0;" : "+l"(acc) : "l"(a), "l"(b));
}
__device__ __forceinline__ ull pack2(float lo, float hi) {
    ull r;
    asm("mov.b64 %0, {%1, %2};" : "=l"(r) : "f"(lo), "f"(hi));
    return r;
}
__device__ __forceinline__ ull splat2(float v) {
    ull r;
    asm("mov.b64 %0, {%1, %1};" : "=l"(r) : "f"(v));
    return r;
}
__device__ __forceinline__ float hsum2(ull p) {
    float lo, hi;
    asm("mov.b64 {%0, %1}, %2;" : "=f"(lo), "=f"(hi) : "l"(p));
    return lo + hi;
}
__device__ __forceinline__ ull fadd2(ull a, ull b) {
    ull r;
    asm("add.rn.f32x2 %0, %1, %2;" : "=l"(r) : "l"(a), "l"(b));
    return r;
}

// named barrier over 256 threads (id 1 for half 0, id 2 for half 1)
#define BARX(id) asm volatile("bar.sync %0, 256;" :: "r"(id) : "memory")

// ---------------------------------------------------------------------------
// K0: counting sort rows by seq_len (descending, LPT) + reset work counter.
// ---------------------------------------------------------------------------
__global__ void sort_kernel(const int* __restrict__ seq_lens) {
    __shared__ int hist[256];
    __shared__ int offs[256];
    int tid = threadIdx.x;
    hist[tid] = 0;
    __syncthreads();
    for (int r = tid; r < B_DIM; r += 256) {
        int L = seq_lens[r];
        L = min(max(L, 0), 255);
        atomicAdd(&hist[L], 1);
    }
    __syncthreads();
    if (tid == 0) {
        int run = 0;
        for (int k = 255; k >= 0; k--) { offs[k] = run; run += hist[k]; }
        g_counter = 0;
    }
    __syncthreads();
    for (int r = tid; r < B_DIM; r += 256) {
        int L = seq_lens[r];
        L = min(max(L, 0), 255);
        int pos = atomicAdd(&offs[L], 1);
        g_perm[pos] = r;
    }
}

// ---------------------------------------------------------------------------
// K1: projection (FFMA2).  Xbuf[b,t,0:256] = emb @ Wg_x + gb,
//                          Xbuf[b,t,256:384] = emb @ Wc_x + cb.
// 512 threads, tile = 64 t-rows x 384 cols.
// ---------------------------------------------------------------------------
__global__ void __launch_bounds__(512) proj_kernel(
    const int* __restrict__ item_his,
    const int* __restrict__ seq_lens,
    const float* __restrict__ embedding,
    const float* __restrict__ gate_kernel,
    const float* __restrict__ gate_bias,
    const float* __restrict__ cand_kernel,
    const float* __restrict__ cand_bias)
{
    extern __shared__ float sm[];
    float* Wx = sm;                    // [64][384]
    float* xs = Wx + 64 * XCOLS;       // [64][64]
    float* bs = xs + 64 * 64;          // [384]
    __shared__ int items_s[64];

    int b  = blockIdx.y;
    int t0 = blockIdx.x * 64;
    int len = seq_lens[b];
    if (t0 >= len) return;
    int tid = threadIdx.x;

    for (int idx = tid; idx < 64 * GH; idx += 512) {
        int k = idx >> 8, c = idx & 255;
        Wx[k * XCOLS + c] = gate_kernel[k * GH + c];
    }
    for (int idx = tid; idx < 64 * H_DIM; idx += 512) {
        int k = idx >> 7, c = idx & 127;
        Wx[k * XCOLS + 256 + c] = cand_kernel[k * H_DIM + c];
    }
    if (tid < 256) bs[tid] = gate_bias[tid];
    else if (tid < 384) bs[tid] = cand_bias[tid - 256];
    if (tid < 64) items_s[tid] = item_his[b * T_DIM + t0 + tid];
    __syncthreads();

    for (int e = tid; e < 64 * 64; e += 512) {
        int rr = e >> 6, k = e & 63;
        xs[e] = embedding[items_s[rr] * 64 + k];
    }
    __syncthreads();

    int tc = tid & 31;     // column pair base = 2*tc
    int tr = tid >> 5;     // row base (0..15), rows tr + 16*ri
    ull acc[4][6];
    #pragma unroll
    for (int ri = 0; ri < 4; ri++)
        #pragma unroll
        for (int ci = 0; ci < 6; ci++) acc[ri][ci] = 0ULL;

    #pragma unroll 4
    for (int k = 0; k < 64; k++) {
        ull A0 = splat2(xs[(tr + 0)  * 64 + k]);
        ull A1 = splat2(xs[(tr + 16) * 64 + k]);
        ull A2 = splat2(xs[(tr + 32) * 64 + k]);
        ull A3 = splat2(xs[(tr + 48) * 64 + k]);
        const float* wrow = Wx + k * XCOLS + 2 * tc;
        #pragma unroll
        for (int ci = 0; ci < 6; ci++) {
            ull w = *(const ull*)(wrow + 64 * ci);
            ffma2(acc[0][ci], A0, w);
            ffma2(acc[1][ci], A1, w);
            ffma2(acc[2][ci], A2, w);
            ffma2(acc[3][ci], A3, w);
        }
    }

    #pragma unroll
    for (int ri = 0; ri < 4; ri++) {
        int t = t0 + tr + 16 * ri;
        float* dst = g_Xbuf + (size_t)(b * T_DIM + t) * XCOLS;
        #pragma unroll
        for (int ci = 0; ci < 6; ci++) {
            int c = 2 * tc + 64 * ci;
            ull bias2 = *(const ull*)(bs + c);
            *(ull*)(dst + c) = fadd2(acc[ri][ci], bias2);
        }
    }
}

// ---------------------------------------------------------------------------
// K2: persistent GRU, 512 threads = TWO independent 256-thread halves, each
// processing its own 4-row group with the R2 read-once dataflow:
//   gate: thread j -> col j, 4 rows, full k (weights read once per step)
//   cand: thread (i, h2) -> k-half partials for all 4 rows, exchange, combine
// Halves synchronize with named barriers only (no cross-half coupling).
// Shared weights in smem; per-half state arrays.
// ---------------------------------------------------------------------------
__global__ void __launch_bounds__(512, 1) gru_kernel(
    const int* __restrict__ seq_lens,
    const float* __restrict__ gate_kernel,
    const float* __restrict__ cand_kernel,
    float* __restrict__ out)
{
    extern __shared__ float sm[];
    float* Ug = sm;                            // [256][KPAD]
    float* Uc = Ug + GH * KPAD;                // [128][KPAD]
    float* st = Uc + H_DIM * KPAD;             // [2][4*512] per-half state
    __shared__ int s_g[2];
    __shared__ int s_b[2][RROWS];
    __shared__ int s_len[2][RROWS];

    int tid  = threadIdx.x;
    int hid  = tid >> 8;       // half id: 0 or 1
    int ltid = tid & 255;      // lane within half
    int bar  = hid + 1;        // named barrier id

    // stage transposed recurrent weights (whole block, once)
    for (int idx = tid; idx < H_DIM * GH; idx += 512) {
        int k = idx >> 8, j = idx & 255;
        Ug[j * KPAD + k] = gate_kernel[(D_DIM + k) * GH + j];
    }
    for (int idx = tid; idx < H_DIM * H_DIM; idx += 512) {
        int k = idx >> 7, i = idx & 127;
        Uc[i * KPAD + k] = cand_kernel[(D_DIM + k) * H_DIM + i];
    }

    float* h_s    = st + hid * 2048;           // [4][128]
    float* rh_s   = h_s + 512;                 // [4][128]
    float* u_s    = rh_s + 512;                // [4][128]
    float* part_s = u_s + 512;                 // [4][128]

    int j    = ltid;
    int i    = ltid & 127;
    int h2   = ltid >> 7;                      // k-half for cand; row-owner pair
    const ulonglong2* Ug2 = (const ulonglong2*)(Ug + j * KPAD);
    const ulonglong2* Uc2 = (const ulonglong2*)(Uc + i * KPAD + h2 * 64);
    const ulonglong2* h20 = (const ulonglong2*)(h_s);
    const ulonglong2* h21 = h20 + (H_DIM / 4);
    const ulonglong2* h22 = h21 + (H_DIM / 4);
    const ulonglong2* h23 = h22 + (H_DIM / 4);
    const ulonglong2* rh20 = (const ulonglong2*)(rh_s + 0 * H_DIM + h2 * 64);
    const ulonglong2* rh21 = (const ulonglong2*)(rh_s + 1 * H_DIM + h2 * 64);
    const ulonglong2* rh22 = (const ulonglong2*)(rh_s + 2 * H_DIM + h2 * 64);
    const ulonglong2* rh23 = (const ulonglong2*)(rh_s + 3 * H_DIM + h2 * 64);
    float* hA = h_s + (2 * h2) * H_DIM;        // owned rows for epilogue
    float* hB = hA + H_DIM;
    __syncthreads();

    while (true) {
        if (ltid == 0) s_g[hid] = atomicAdd(&g_counter, 1);
        BARX(bar);
        int g = s_g[hid];
        if (g >= NGROUPS) break;

        if (ltid < RROWS) {
            int row = g_perm[g * RROWS + ltid];
            s_b[hid][ltid]   = row;
            s_len[hid][ltid] = min(max(seq_lens[row], 0), T_DIM);
        }
        for (int e = ltid; e < RROWS * H_DIM; e += 256) h_s[e] = 0.0f;
        BARX(bar);

        int len0 = s_len[hid][0], len1 = s_len[hid][1];
        int len2 = s_len[hid][2], len3 = s_len[hid][3];
        int L = max(max(len0, len1), max(len2, len3));
        int lenA = h2 ? len2 : len0;
        int lenB = h2 ? len3 : len1;

        const float* xg0 = g_Xbuf + s_b[hid][0] * (T_DIM * XCOLS) + j;
        const float* xg1 = g_Xbuf + s_b[hid][1] * (T_DIM * XCOLS) + j;
        const float* xg2 = g_Xbuf + s_b[hid][2] * (T_DIM * XCOLS) + j;
        const float* xg3 = g_Xbuf + s_b[hid][3] * (T_DIM * XCOLS) + j;
        const float* xcA = g_Xbuf + s_b[hid][2 * h2]     * (T_DIM * XCOLS) + 256 + i;
        const float* xcB = g_Xbuf + s_b[hid][2 * h2 + 1] * (T_DIM * XCOLS) + 256 + i;

        for (int t = 0; t < L; t++) {
            // early global loads (consumed after the k-loops)
            float vg0 = xg0[t * XCOLS];
            float vg1 = xg1[t * XCOLS];
            float vg2 = xg2[t * XCOLS];
            float vg3 = xg3[t * XCOLS];
            float vcA = xcA[t * XCOLS];
            float vcB = xcB[t * XCOLS];

            // gate GEMM (col j, 4 rows) — weights read once
            ull a0 = pack2(vg0, 0.0f);
            ull a1 = pack2(vg1, 0.0f);
            ull a2 = pack2(vg2, 0.0f);
            ull a3 = pack2(vg3, 0.0f);
            #pragma unroll 8
            for (int k4 = 0; k4 < H_DIM / 4; k4++) {
                ulonglong2 w  = Ug2[k4];
                ulonglong2 v0 = h20[k4];
                ffma2(a0, v0.x, w.x); ffma2(a0, v0.y, w.y);
                ulonglong2 v1 = h21[k4];
                ffma2(a1, v1.x, w.x); ffma2(a1, v1.y, w.y);
                ulonglong2 v2 = h22[k4];
                ffma2(a2, v2.x, w.x); ffma2(a2, v2.y, w.y);
                ulonglong2 v3 = h23[k4];
                ffma2(a3, v3.x, w.x); ffma2(a3, v3.y, w.y);
            }
            float s0 = fast_sigmoid(hsum2(a0));
            float s1 = fast_sigmoid(hsum2(a1));
            float s2 = fast_sigmoid(hsum2(a2));
            float s3 = fast_sigmoid(hsum2(a3));

            if (h2 == 0) {             // r-gate columns 0..127
                rh_s[0 * H_DIM + j] = s0 * h_s[0 * H_DIM + j];
                rh_s[1 * H_DIM + j] = s1 * h_s[1 * H_DIM + j];
                rh_s[2 * H_DIM + j] = s2 * h_s[2 * H_DIM + j];
                rh_s[3 * H_DIM + j] = s3 * h_s[3 * H_DIM + j];
            } else {                   // u-gate columns 128..255
                u_s[0 * H_DIM + i] = s0;
                u_s[1 * H_DIM + i] = s1;
                u_s[2 * H_DIM + i] = s2;
                u_s[3 * H_DIM + i] = s3;
            }
            BARX(bar);

            // cand GEMM partials: k in [64*h2, 64*h2+64), all 4 rows (read once)
            ull c0 = 0ULL, c1 = 0ULL, c2 = 0ULL, c3 = 0ULL;
            #pragma unroll 8
            for (int k4 = 0; k4 < 16; k4++) {
                ulonglong2 w  = Uc2[k4];
                ulonglong2 v0 = rh20[k4];
                ffma2(c0, v0.x, w.x); ffma2(c0, v0.y, w.y);
                ulonglong2 v1 = rh21[k4];
                ffma2(c1, v1.x, w.x); ffma2(c1, v1.y, w.y);
                ulonglong2 v2 = rh22[k4];
                ffma2(c2, v2.x, w.x); ffma2(c2, v2.y, w.y);
                ulonglong2 v3 = rh23[k4];
                ffma2(c3, v3.x, w.x); ffma2(c3, v3.y, w.y);
            }
            float p0 = hsum2(c0), p1 = hsum2(c1), p2 = hsum2(c2), p3 = hsum2(c3);
            float ownA, ownB;
            if (h2 == 0) {             // owns rows 0,1; exports rows 2,3
                part_s[2 * H_DIM + i] = p2;
                part_s[3 * H_DIM + i] = p3;
                ownA = p0; ownB = p1;
            } else {                   // owns rows 2,3; exports rows 0,1
                part_s[0 * H_DIM + i] = p0;
                part_s[1 * H_DIM + i] = p1;
                ownA = p2; ownB = p3;
            }
            BARX(bar);

            {
                float c  = fast_tanh(ownA + part_s[(2 * h2) * H_DIM + i] + vcA);
                float u  = u_s[(2 * h2) * H_DIM + i];
                float hv = hA[i];
                float hn = fmaf(u, hv - c, c);   // u*h + (1-u)*c
                if (t < lenA) hA[i] = hn;
            }
            {
                float c  = fast_tanh(ownB + part_s[(2 * h2 + 1) * H_DIM + i] + vcB);
                float u  = u_s[(2 * h2 + 1) * H_DIM + i];
                float hv = hB[i];
                float hn = fmaf(u, hv - c, c);
                if (t < lenB) hB[i] = hn;
            }
            BARX(bar);
        }

        out[s_b[hid][2 * h2]     * H_DIM + i] = hA[i];
        out[s_b[hid][2 * h2 + 1] * H_DIM + i] = hB[i];
        BARX(bar);
    }
}

// ---------------------------------------------------------------------------
extern "C" void kernel_launch(void* const* d_in, const int* in_sizes, int n_in,
                              void* d_out, int out_size) {
    (void)in_sizes; (void)n_in; (void)out_size;
    const int*   item_his    = (const int*)  d_in[0];
    const int*   seq_lens    = (const int*)  d_in[1];
    const float* embedding   = (const float*)d_in[2];
    const float* gate_kernel = (const float*)d_in[3];
    const float* gate_bias   = (const float*)d_in[4];
    const float* cand_kernel = (const float*)d_in[5];
    const float* cand_bias   = (const float*)d_in[6];
    float*       out         = (float*)d_out;

    const int smem_proj = (64 * XCOLS + 64 * 64 + XCOLS) * 4;                 // ~116 KB
    const int smem_gru  = (GH * KPAD + H_DIM * KPAD + 2 * 2048) * 4;          // ~219 KB
    cudaFuncSetAttribute(proj_kernel, cudaFuncAttributeMaxDynamicSharedMemorySize, smem_proj);
    cudaFuncSetAttribute(gru_kernel,  cudaFuncAttributeMaxDynamicSharedMemorySize, smem_gru);

    sort_kernel<<<1, 256>>>(seq_lens);
    proj_kernel<<<dim3(T_DIM / 64, B_DIM), 512, smem_proj>>>(
        item_his, seq_lens, embedding, gate_kernel, gate_bias, cand_kernel, cand_bias);
    gru_kernel<<<148, 512, smem_gru>>>(seq_lens, gate_kernel, cand_kernel, out);
}

// round 5
// speedup vs baseline: 1.2108x; 1.2108x over previous
#include <cuda_runtime.h>

#define B_DIM 1024
#define T_DIM 256
#define D_DIM 64
#define H_DIM 128
#define GH 256          // 2H
#define XCOLS 384       // 256 gate cols + 128 cand cols
#define RROWS 4
#define NGROUPS (B_DIM / RROWS)   // 256

// Scratch (device globals: no allocation allowed).
static __device__ float g_Xbuf[(size_t)B_DIM * T_DIM * XCOLS]; // ~402 MB
static __device__ int   g_perm[B_DIM];
static __device__ int   g_counter;

typedef unsigned long long ull;

__device__ __forceinline__ float fast_sigmoid(float z) {
    return __fdividef(1.0f, 1.0f + __expf(-z));
}
__device__ __forceinline__ float fast_tanh(float z) {
    return 1.0f - __fdividef(2.0f, __expf(2.0f * z) + 1.0f);
}

// packed fp32x2 helpers (Blackwell FFMA2 — PTX-only, exact fp32)
__device__ __forceinline__ void ffma2(ull& acc, ull a, ull b) {
    asm("fma.rn.f32x2 %0, %1, %2, %0;" : "+l"(acc) : "l"(a), "l"(b));
}
__device__ __forceinline__ ull pack2(float lo, float hi) {
    ull r;
    asm("mov.b64 %0, {%1, %2};" : "=l"(r) : "f"(lo), "f"(hi));
    return r;
}
__device__ __forceinline__ ull splat2(float v) {
    ull r;
    asm("mov.b64 %0, {%1, %1};" : "=l"(r) : "f"(v));
    return r;
}
__device__ __forceinline__ float hsum2(ull p) {
    float lo, hi;
    asm("mov.b64 {%0, %1}, %2;" : "=f"(lo), "=f"(hi) : "l"(p));
    return lo + hi;
}
__device__ __forceinline__ ull fadd2(ull a, ull b) {
    ull r;
    asm("add.rn.f32x2 %0, %1, %2;" : "=l"(r) : "l"(a), "l"(b));
    return r;
}

// ---------------------------------------------------------------------------
// K0: counting sort rows by seq_len (descending, LPT) + reset work counter.
// ---------------------------------------------------------------------------
__global__ void sort_kernel(const int* __restrict__ seq_lens) {
    __shared__ int hist[256];
    __shared__ int offs[256];
    int tid = threadIdx.x;
    hist[tid] = 0;
    __syncthreads();
    for (int r = tid; r < B_DIM; r += 256) {
        int L = seq_lens[r];
        L = min(max(L, 0), 255);
        atomicAdd(&hist[L], 1);
    }
    __syncthreads();
    if (tid == 0) {
        int run = 0;
        for (int k = 255; k >= 0; k--) { offs[k] = run; run += hist[k]; }
        g_counter = 0;
    }
    __syncthreads();
    for (int r = tid; r < B_DIM; r += 256) {
        int L = seq_lens[r];
        L = min(max(L, 0), 255);
        int pos = atomicAdd(&offs[L], 1);
        g_perm[pos] = r;
    }
}

// ---------------------------------------------------------------------------
// K1: projection (FFMA2).  Xbuf[b,t,0:256] = emb @ Wg_x + gb,
//                          Xbuf[b,t,256:384] = emb @ Wc_x + cb.
// 512 threads, tile = 64 t-rows x 384 cols.
// ---------------------------------------------------------------------------
__global__ void __launch_bounds__(512) proj_kernel(
    const int* __restrict__ item_his,
    const int* __restrict__ seq_lens,
    const float* __restrict__ embedding,
    const float* __restrict__ gate_kernel,
    const float* __restrict__ gate_bias,
    const float* __restrict__ cand_kernel,
    const float* __restrict__ cand_bias)
{
    extern __shared__ float sm[];
    float* Wx = sm;                    // [64][384]
    float* xs = Wx + 64 * XCOLS;       // [64][64]
    float* bs = xs + 64 * 64;          // [384]
    __shared__ int items_s[64];

    int b  = blockIdx.y;
    int t0 = blockIdx.x * 64;
    int len = seq_lens[b];
    if (t0 >= len) return;
    int tid = threadIdx.x;

    for (int idx = tid; idx < 64 * GH; idx += 512) {
        int k = idx >> 8, c = idx & 255;
        Wx[k * XCOLS + c] = gate_kernel[k * GH + c];
    }
    for (int idx = tid; idx < 64 * H_DIM; idx += 512) {
        int k = idx >> 7, c = idx & 127;
        Wx[k * XCOLS + 256 + c] = cand_kernel[k * H_DIM + c];
    }
    if (tid < 256) bs[tid] = gate_bias[tid];
    else if (tid < 384) bs[tid] = cand_bias[tid - 256];
    if (tid < 64) items_s[tid] = item_his[b * T_DIM + t0 + tid];
    __syncthreads();

    for (int e = tid; e < 64 * 64; e += 512) {
        int rr = e >> 6, k = e & 63;
        xs[e] = embedding[items_s[rr] * 64 + k];
    }
    __syncthreads();

    int tc = tid & 31;     // column pair base = 2*tc
    int tr = tid >> 5;     // row base (0..15), rows tr + 16*ri
    ull acc[4][6];
    #pragma unroll
    for (int ri = 0; ri < 4; ri++)
        #pragma unroll
        for (int ci = 0; ci < 6; ci++) acc[ri][ci] = 0ULL;

    #pragma unroll 4
    for (int k = 0; k < 64; k++) {
        ull A0 = splat2(xs[(tr + 0)  * 64 + k]);
        ull A1 = splat2(xs[(tr + 16) * 64 + k]);
        ull A2 = splat2(xs[(tr + 32) * 64 + k]);
        ull A3 = splat2(xs[(tr + 48) * 64 + k]);
        const float* wrow = Wx + k * XCOLS + 2 * tc;
        #pragma unroll
        for (int ci = 0; ci < 6; ci++) {
            ull w = *(const ull*)(wrow + 64 * ci);
            ffma2(acc[0][ci], A0, w);
            ffma2(acc[1][ci], A1, w);
            ffma2(acc[2][ci], A2, w);
            ffma2(acc[3][ci], A3, w);
        }
    }

    #pragma unroll
    for (int ri = 0; ri < 4; ri++) {
        int t = t0 + tr + 16 * ri;
        float* dst = g_Xbuf + (size_t)(b * T_DIM + t) * XCOLS;
        #pragma unroll
        for (int ci = 0; ci < 6; ci++) {
            int c = 2 * tc + 64 * ci;
            ull bias2 = *(const ull*)(bs + c);
            *(ull*)(dst + c) = fadd2(acc[ri][ci], bias2);
        }
    }
}

// ---------------------------------------------------------------------------
// K2: persistent GRU, 384 threads, ONE 4-row group at a time, recurrent
// weights held in REGISTERS (64 packed f32x2 per thread = its column).
//   threads [0,256):  gate col j = tid  (r-gate j<128, u-gate j>=128)
//   threads [256,384): cand col i = tid-256
// Per step, smem traffic = h/rh broadcasts + tiny u/h accesses only.
// ---------------------------------------------------------------------------
__global__ void __launch_bounds__(384, 1) gru_kernel(
    const int* __restrict__ seq_lens,
    const float* __restrict__ gate_kernel,
    const float* __restrict__ cand_kernel,
    float* __restrict__ out)
{
    __shared__ float h_s[RROWS * H_DIM];
    __shared__ float rh_s[RROWS * H_DIM];
    __shared__ float u_s[RROWS * H_DIM];
    __shared__ int s_g;
    __shared__ int s_b[RROWS];
    __shared__ int s_len[RROWS];

    int tid = threadIdx.x;
    bool is_gate = tid < 256;
    int j = is_gate ? tid : 0;          // gate column
    int i = is_gate ? 0 : (tid - 256);  // cand column

    // Load this thread's weight column into registers, packed over k-pairs.
    ull w2[64];
    if (is_gate) {
        #pragma unroll
        for (int k2 = 0; k2 < 64; k2++) {
            float lo = gate_kernel[(D_DIM + 2 * k2)     * GH + j];
            float hi = gate_kernel[(D_DIM + 2 * k2 + 1) * GH + j];
            w2[k2] = pack2(lo, hi);
        }
    } else {
        #pragma unroll
        for (int k2 = 0; k2 < 64; k2++) {
            float lo = cand_kernel[(D_DIM + 2 * k2)     * H_DIM + i];
            float hi = cand_kernel[(D_DIM + 2 * k2 + 1) * H_DIM + i];
            w2[k2] = pack2(lo, hi);
        }
    }

    while (true) {
        if (tid == 0) s_g = atomicAdd(&g_counter, 1);
        __syncthreads();
        int g = s_g;
        if (g >= NGROUPS) break;

        if (tid < RROWS) {
            int row = g_perm[g * RROWS + tid];
            s_b[tid]   = row;
            s_len[tid] = min(max(seq_lens[row], 0), T_DIM);
        }
        for (int e = tid; e < RROWS * H_DIM; e += 384) h_s[e] = 0.0f;
        __syncthreads();

        int len0 = s_len[0], len1 = s_len[1], len2 = s_len[2], len3 = s_len[3];
        int L = max(max(len0, len1), max(len2, len3));

        // 32-bit element offsets into g_Xbuf (total 100M floats < 2^31)
        int col = is_gate ? j : (256 + i);
        int x0 = s_b[0] * (T_DIM * XCOLS) + col;
        int x1 = s_b[1] * (T_DIM * XCOLS) + col;
        int x2 = s_b[2] * (T_DIM * XCOLS) + col;
        int x3 = s_b[3] * (T_DIM * XCOLS) + col;

        float v0 = 0.f, v1 = 0.f, v2 = 0.f, v3 = 0.f;

        for (int t = 0; t < L; t++) {
            int toff = t * XCOLS;
            if (is_gate) {
                v0 = g_Xbuf[x0 + toff];
                v1 = g_Xbuf[x1 + toff];
                v2 = g_Xbuf[x2 + toff];
                v3 = g_Xbuf[x3 + toff];

                ull a0 = 0ULL, a1 = 0ULL, a2 = 0ULL, a3 = 0ULL;
                #pragma unroll
                for (int k4 = 0; k4 < 32; k4++) {
                    ulonglong2 hb0 = *(const ulonglong2*)(h_s + 0 * H_DIM + 4 * k4);
                    ffma2(a0, hb0.x, w2[2 * k4]); ffma2(a0, hb0.y, w2[2 * k4 + 1]);
                    ulonglong2 hb1 = *(const ulonglong2*)(h_s + 1 * H_DIM + 4 * k4);
                    ffma2(a1, hb1.x, w2[2 * k4]); ffma2(a1, hb1.y, w2[2 * k4 + 1]);
                    ulonglong2 hb2 = *(const ulonglong2*)(h_s + 2 * H_DIM + 4 * k4);
                    ffma2(a2, hb2.x, w2[2 * k4]); ffma2(a2, hb2.y, w2[2 * k4 + 1]);
                    ulonglong2 hb3 = *(const ulonglong2*)(h_s + 3 * H_DIM + 4 * k4);
                    ffma2(a3, hb3.x, w2[2 * k4]); ffma2(a3, hb3.y, w2[2 * k4 + 1]);
                }
                float s0 = fast_sigmoid(hsum2(a0) + v0);
                float s1 = fast_sigmoid(hsum2(a1) + v1);
                float s2 = fast_sigmoid(hsum2(a2) + v2);
                float s3 = fast_sigmoid(hsum2(a3) + v3);

                if (j < H_DIM) {       // r-gate -> rh
                    rh_s[0 * H_DIM + j] = s0 * h_s[0 * H_DIM + j];
                    rh_s[1 * H_DIM + j] = s1 * h_s[1 * H_DIM + j];
                    rh_s[2 * H_DIM + j] = s2 * h_s[2 * H_DIM + j];
                    rh_s[3 * H_DIM + j] = s3 * h_s[3 * H_DIM + j];
                } else {               // u-gate
                    int jj = j - H_DIM;
                    u_s[0 * H_DIM + jj] = s0;
                    u_s[1 * H_DIM + jj] = s1;
                    u_s[2 * H_DIM + jj] = s2;
                    u_s[3 * H_DIM + jj] = s3;
                }
            } else {
                // prefetch cand x-inputs while gate threads compute
                v0 = g_Xbuf[x0 + toff];
                v1 = g_Xbuf[x1 + toff];
                v2 = g_Xbuf[x2 + toff];
                v3 = g_Xbuf[x3 + toff];
            }
            __syncthreads();

            if (!is_gate) {
                ull a0 = 0ULL, a1 = 0ULL, a2 = 0ULL, a3 = 0ULL;
                #pragma unroll
                for (int k4 = 0; k4 < 32; k4++) {
                    ulonglong2 rb0 = *(const ulonglong2*)(rh_s + 0 * H_DIM + 4 * k4);
                    ffma2(a0, rb0.x, w2[2 * k4]); ffma2(a0, rb0.y, w2[2 * k4 + 1]);
                    ulonglong2 rb1 = *(const ulonglong2*)(rh_s + 1 * H_DIM + 4 * k4);
                    ffma2(a1, rb1.x, w2[2 * k4]); ffma2(a1, rb1.y, w2[2 * k4 + 1]);
                    ulonglong2 rb2 = *(const ulonglong2*)(rh_s + 2 * H_DIM + 4 * k4);
                    ffma2(a2, rb2.x, w2[2 * k4]); ffma2(a2, rb2.y, w2[2 * k4 + 1]);
                    ulonglong2 rb3 = *(const ulonglong2*)(rh_s + 3 * H_DIM + 4 * k4);
                    ffma2(a3, rb3.x, w2[2 * k4]); ffma2(a3, rb3.y, w2[2 * k4 + 1]);
                }
                float c0 = fast_tanh(hsum2(a0) + v0);
                float c1 = fast_tanh(hsum2(a1) + v1);
                float c2 = fast_tanh(hsum2(a2) + v2);
                float c3 = fast_tanh(hsum2(a3) + v3);

                float u0 = u_s[0 * H_DIM + i];
                float u1 = u_s[1 * H_DIM + i];
                float u2 = u_s[2 * H_DIM + i];
                float u3 = u_s[3 * H_DIM + i];
                float hv0 = h_s[0 * H_DIM + i];
                float hv1 = h_s[1 * H_DIM + i];
                float hv2 = h_s[2 * H_DIM + i];
                float hv3 = h_s[3 * H_DIM + i];
                if (t < len0) h_s[0 * H_DIM + i] = fmaf(u0, hv0 - c0, c0);
                if (t < len1) h_s[1 * H_DIM + i] = fmaf(u1, hv1 - c1, c1);
                if (t < len2) h_s[2 * H_DIM + i] = fmaf(u2, hv2 - c2, c2);
                if (t < len3) h_s[3 * H_DIM + i] = fmaf(u3, hv3 - c3, c3);
            }
            __syncthreads();
        }

        if (!is_gate) {
            out[s_b[0] * H_DIM + i] = h_s[0 * H_DIM + i];
            out[s_b[1] * H_DIM + i] = h_s[1 * H_DIM + i];
            out[s_b[2] * H_DIM + i] = h_s[2 * H_DIM + i];
            out[s_b[3] * H_DIM + i] = h_s[3 * H_DIM + i];
        }
        __syncthreads();
    }
}

// ---------------------------------------------------------------------------
extern "C" void kernel_launch(void* const* d_in, const int* in_sizes, int n_in,
                              void* d_out, int out_size) {
    (void)in_sizes; (void)n_in; (void)out_size;
    const int*   item_his    = (const int*)  d_in[0];
    const int*   seq_lens    = (const int*)  d_in[1];
    const float* embedding   = (const float*)d_in[2];
    const float* gate_kernel = (const float*)d_in[3];
    const float* gate_bias   = (const float*)d_in[4];
    const float* cand_kernel = (const float*)d_in[5];
    const float* cand_bias   = (const float*)d_in[6];
    float*       out         = (float*)d_out;

    const int smem_proj = (64 * XCOLS + 64 * 64 + XCOLS) * 4;   // ~116 KB
    cudaFuncSetAttribute(proj_kernel, cudaFuncAttributeMaxDynamicSharedMemorySize, smem_proj);

    sort_kernel<<<1, 256>>>(seq_lens);
    proj_kernel<<<dim3(T_DIM / 64, B_DIM), 512, smem_proj>>>(
        item_his, seq_lens, embedding, gate_kernel, gate_bias, cand_kernel, cand_bias);
    gru_kernel<<<148, 384>>>(seq_lens, gate_kernel, cand_kernel, out);
}

// round 7
// speedup vs baseline: 1.7895x; 1.4780x over previous
#include <cuda_runtime.h>

#define B_DIM 1024
#define T_DIM 256
#define D_DIM 64
#define H_DIM 128
#define GH 256          // 2H
#define XCOLS 384       // 256 gate cols + 128 cand cols
#define RROWS 4
#define NGROUPS (B_DIM / RROWS)   // 256

// Scratch (device globals: no allocation allowed).
static __device__ float g_Xbuf[(size_t)B_DIM * T_DIM * XCOLS]; // ~402 MB
static __device__ int   g_perm[B_DIM];
static __device__ int   g_counter;

typedef unsigned long long ull;

__device__ __forceinline__ float fast_sigmoid(float z) {
    return __fdividef(1.0f, 1.0f + __expf(-z));
}
__device__ __forceinline__ float fast_tanh(float z) {
    return 1.0f - __fdividef(2.0f, __expf(2.0f * z) + 1.0f);
}

// packed fp32x2 helpers (Blackwell FFMA2 — PTX-only, exact fp32)
__device__ __forceinline__ void ffma2(ull& acc, ull a, ull b) {
    asm("fma.rn.f32x2 %0, %1, %2, %0;" : "+l"(acc) : "l"(a), "l"(b));
}
__device__ __forceinline__ ull pack2(float lo, float hi) {
    ull r;
    asm("mov.b64 %0, {%1, %2};" : "=l"(r) : "f"(lo), "f"(hi));
    return r;
}
__device__ __forceinline__ ull splat2(float v) {
    ull r;
    asm("mov.b64 %0, {%1, %1};" : "=l"(r) : "f"(v));
    return r;
}
__device__ __forceinline__ float hsum2(ull p) {
    float lo, hi;
    asm("mov.b64 {%0, %1}, %2;" : "=f"(lo), "=f"(hi) : "l"(p));
    return lo + hi;
}
__device__ __forceinline__ ull fadd2(ull a, ull b) {
    ull r;
    asm("add.rn.f32x2 %0, %1, %2;" : "=l"(r) : "l"(a), "l"(b));
    return r;
}

// ---------------------------------------------------------------------------
// K0: counting sort rows by seq_len (descending, LPT) + reset work counter.
// ---------------------------------------------------------------------------
__global__ void sort_kernel(const int* __restrict__ seq_lens) {
    __shared__ int hist[256];
    __shared__ int offs[256];
    int tid = threadIdx.x;
    hist[tid] = 0;
    __syncthreads();
    for (int r = tid; r < B_DIM; r += 256) {
        int L = seq_lens[r];
        L = min(max(L, 0), 255);
        atomicAdd(&hist[L], 1);
    }
    __syncthreads();
    if (tid == 0) {
        int run = 0;
        for (int k = 255; k >= 0; k--) { offs[k] = run; run += hist[k]; }
        g_counter = 0;
    }
    __syncthreads();
    for (int r = tid; r < B_DIM; r += 256) {
        int L = seq_lens[r];
        L = min(max(L, 0), 255);
        int pos = atomicAdd(&offs[L], 1);
        g_perm[pos] = r;
    }
}

// ---------------------------------------------------------------------------
// K1: projection (FFMA2).  Xbuf[b,t,0:256] = emb @ Wg_x + gb,
//                          Xbuf[b,t,256:384] = emb @ Wc_x + cb.
// 512 threads, tile = 64 t-rows x 384 cols.
// ---------------------------------------------------------------------------
__global__ void __launch_bounds__(512) proj_kernel(
    const int* __restrict__ item_his,
    const int* __restrict__ seq_lens,
    const float* __restrict__ embedding,
    const float* __restrict__ gate_kernel,
    const float* __restrict__ gate_bias,
    const float* __restrict__ cand_kernel,
    const float* __restrict__ cand_bias)
{
    extern __shared__ float sm[];
    float* Wx = sm;                    // [64][384]
    float* xs = Wx + 64 * XCOLS;       // [64][64]
    float* bs = xs + 64 * 64;          // [384]
    __shared__ int items_s[64];

    int b  = blockIdx.y;
    int t0 = blockIdx.x * 64;
    int len = seq_lens[b];
    if (t0 >= len) return;
    int tid = threadIdx.x;

    for (int idx = tid; idx < 64 * GH; idx += 512) {
        int k = idx >> 8, c = idx & 255;
        Wx[k * XCOLS + c] = gate_kernel[k * GH + c];
    }
    for (int idx = tid; idx < 64 * H_DIM; idx += 512) {
        int k = idx >> 7, c = idx & 127;
        Wx[k * XCOLS + 256 + c] = cand_kernel[k * H_DIM + c];
    }
    if (tid < 256) bs[tid] = gate_bias[tid];
    else if (tid < 384) bs[tid] = cand_bias[tid - 256];
    if (tid < 64) items_s[tid] = item_his[b * T_DIM + t0 + tid];
    __syncthreads();

    for (int e = tid; e < 64 * 64; e += 512) {
        int rr = e >> 6, k = e & 63;
        xs[e] = embedding[items_s[rr] * 64 + k];
    }
    __syncthreads();

    int tc = tid & 31;     // column pair base = 2*tc
    int tr = tid >> 5;     // row base (0..15), rows tr + 16*ri
    ull acc[4][6];
    #pragma unroll
    for (int ri = 0; ri < 4; ri++)
        #pragma unroll
        for (int ci = 0; ci < 6; ci++) acc[ri][ci] = 0ULL;

    #pragma unroll 4
    for (int k = 0; k < 64; k++) {
        ull A0 = splat2(xs[(tr + 0)  * 64 + k]);
        ull A1 = splat2(xs[(tr + 16) * 64 + k]);
        ull A2 = splat2(xs[(tr + 32) * 64 + k]);
        ull A3 = splat2(xs[(tr + 48) * 64 + k]);
        const float* wrow = Wx + k * XCOLS + 2 * tc;
        #pragma unroll
        for (int ci = 0; ci < 6; ci++) {
            ull w = *(const ull*)(wrow + 64 * ci);
            ffma2(acc[0][ci], A0, w);
            ffma2(acc[1][ci], A1, w);
            ffma2(acc[2][ci], A2, w);
            ffma2(acc[3][ci], A3, w);
        }
    }

    #pragma unroll
    for (int ri = 0; ri < 4; ri++) {
        int t = t0 + tr + 16 * ri;
        float* dst = g_Xbuf + (size_t)(b * T_DIM + t) * XCOLS;
        #pragma unroll
        for (int ci = 0; ci < 6; ci++) {
            int c = 2 * tc + 64 * ci;
            ull bias2 = *(const ull*)(bs + c);
            *(ull*)(dst + c) = fadd2(acc[ri][ci], bias2);
        }
    }
}

// ---------------------------------------------------------------------------
// K2: persistent GRU — R2 dataflow + REGISTER-RESIDENT weights.
// 256 threads, one 4-row group at a time.
//   gate: thread j holds Ug col j (64 packed f32x2 regs), computes col j
//         for all 4 rows. h reads are smem broadcasts.
//   cand: thread (i = j&127, half = j>>7) holds Uc[i][k-half] (32 packed),
//         computes k-half partials for 4 rows; exchange via smem; owner half
//         combines + tanh + h-update for rows 2*half, 2*half+1.
// Zero weight smem traffic in the loop.
// ---------------------------------------------------------------------------
__global__ void __launch_bounds__(256, 1) gru_kernel(
    const int* __restrict__ seq_lens,
    const float* __restrict__ gate_kernel,
    const float* __restrict__ cand_kernel,
    float* __restrict__ out)
{
    __shared__ float h_s[RROWS * H_DIM];
    __shared__ float rh_s[RROWS * H_DIM];
    __shared__ float u_s[RROWS * H_DIM];
    __shared__ float part_s[RROWS * H_DIM];
    __shared__ int s_g;
    __shared__ int s_b[RROWS];
    __shared__ int s_len[RROWS];

    int tid  = threadIdx.x;
    int j    = tid;             // gate column
    int i    = tid & 127;       // cand column
    int half = tid >> 7;        // cand k-half & row-owner pair

    // Gate weight column j in registers (64 packed k-pairs)
    ull wg[64];
    #pragma unroll
    for (int k2 = 0; k2 < 64; k2++) {
        wg[k2] = pack2(gate_kernel[(D_DIM + 2 * k2)     * GH + j],
                       gate_kernel[(D_DIM + 2 * k2 + 1) * GH + j]);
    }
    // Cand weight half-column in registers (32 packed k-pairs)
    ull wc[32];
    #pragma unroll
    for (int k2 = 0; k2 < 32; k2++) {
        int k = 64 * half + 2 * k2;
        wc[k2] = pack2(cand_kernel[(D_DIM + k)     * H_DIM + i],
                       cand_kernel[(D_DIM + k + 1) * H_DIM + i]);
    }

    const ulonglong2* h20 = (const ulonglong2*)(h_s);
    const ulonglong2* h21 = h20 + (H_DIM / 4);
    const ulonglong2* h22 = h21 + (H_DIM / 4);
    const ulonglong2* h23 = h22 + (H_DIM / 4);
    const ulonglong2* rh20 = (const ulonglong2*)(rh_s + 0 * H_DIM + half * 64);
    const ulonglong2* rh21 = (const ulonglong2*)(rh_s + 1 * H_DIM + half * 64);
    const ulonglong2* rh22 = (const ulonglong2*)(rh_s + 2 * H_DIM + half * 64);
    const ulonglong2* rh23 = (const ulonglong2*)(rh_s + 3 * H_DIM + half * 64);
    float* hA = h_s + (2 * half) * H_DIM;      // owned rows
    float* hB = hA + H_DIM;

    while (true) {
        if (tid == 0) s_g = atomicAdd(&g_counter, 1);
        __syncthreads();
        int g = s_g;
        if (g >= NGROUPS) break;

        if (tid < RROWS) {
            int row = g_perm[g * RROWS + tid];
            s_b[tid]   = row;
            s_len[tid] = min(max(seq_lens[row], 0), T_DIM);
        }
        for (int e = tid; e < RROWS * H_DIM; e += 256) h_s[e] = 0.0f;
        __syncthreads();

        int len0 = s_len[0], len1 = s_len[1], len2 = s_len[2], len3 = s_len[3];
        int L = max(max(len0, len1), max(len2, len3));
        int lenA = half ? len2 : len0;
        int lenB = half ? len3 : len1;

        // 32-bit element offsets into g_Xbuf (100M floats < 2^31)
        int x0 = s_b[0] * (T_DIM * XCOLS) + j;
        int x1 = s_b[1] * (T_DIM * XCOLS) + j;
        int x2 = s_b[2] * (T_DIM * XCOLS) + j;
        int x3 = s_b[3] * (T_DIM * XCOLS) + j;
        int xA = s_b[2 * half]     * (T_DIM * XCOLS) + 256 + i;
        int xB = s_b[2 * half + 1] * (T_DIM * XCOLS) + 256 + i;

        for (int t = 0; t < L; t++) {
            int toff = t * XCOLS;
            // early global loads (consumed after the k-loops)
            float vg0 = g_Xbuf[x0 + toff];
            float vg1 = g_Xbuf[x1 + toff];
            float vg2 = g_Xbuf[x2 + toff];
            float vg3 = g_Xbuf[x3 + toff];
            float vcA = g_Xbuf[xA + toff];
            float vcB = g_Xbuf[xB + toff];

            // gate GEMM (col j, 4 rows) — weights in regs, h broadcast LDS
            ull a0 = 0ULL, a1 = 0ULL, a2 = 0ULL, a3 = 0ULL;
            #pragma unroll
            for (int k4 = 0; k4 < H_DIM / 4; k4++) {
                ulonglong2 v0 = h20[k4];
                ffma2(a0, v0.x, wg[2 * k4]); ffma2(a0, v0.y, wg[2 * k4 + 1]);
                ulonglong2 v1 = h21[k4];
                ffma2(a1, v1.x, wg[2 * k4]); ffma2(a1, v1.y, wg[2 * k4 + 1]);
                ulonglong2 v2 = h22[k4];
                ffma2(a2, v2.x, wg[2 * k4]); ffma2(a2, v2.y, wg[2 * k4 + 1]);
                ulonglong2 v3 = h23[k4];
                ffma2(a3, v3.x, wg[2 * k4]); ffma2(a3, v3.y, wg[2 * k4 + 1]);
            }
            float s0 = fast_sigmoid(hsum2(a0) + vg0);
            float s1 = fast_sigmoid(hsum2(a1) + vg1);
            float s2 = fast_sigmoid(hsum2(a2) + vg2);
            float s3 = fast_sigmoid(hsum2(a3) + vg3);

            if (half == 0) {           // r-gate columns 0..127
                rh_s[0 * H_DIM + j] = s0 * h_s[0 * H_DIM + j];
                rh_s[1 * H_DIM + j] = s1 * h_s[1 * H_DIM + j];
                rh_s[2 * H_DIM + j] = s2 * h_s[2 * H_DIM + j];
                rh_s[3 * H_DIM + j] = s3 * h_s[3 * H_DIM + j];
            } else {                   // u-gate columns 128..255
                u_s[0 * H_DIM + i] = s0;
                u_s[1 * H_DIM + i] = s1;
                u_s[2 * H_DIM + i] = s2;
                u_s[3 * H_DIM + i] = s3;
            }
            __syncthreads();

            // cand GEMM partials: k in [64*half, 64*half+64), all 4 rows
            ull c0 = 0ULL, c1 = 0ULL, c2 = 0ULL, c3 = 0ULL;
            #pragma unroll
            for (int k4 = 0; k4 < 16; k4++) {
                ulonglong2 v0 = rh20[k4];
                ffma2(c0, v0.x, wc[2 * k4]); ffma2(c0, v0.y, wc[2 * k4 + 1]);
                ulonglong2 v1 = rh21[k4];
                ffma2(c1, v1.x, wc[2 * k4]); ffma2(c1, v1.y, wc[2 * k4 + 1]);
                ulonglong2 v2 = rh22[k4];
                ffma2(c2, v2.x, wc[2 * k4]); ffma2(c2, v2.y, wc[2 * k4 + 1]);
                ulonglong2 v3 = rh23[k4];
                ffma2(c3, v3.x, wc[2 * k4]); ffma2(c3, v3.y, wc[2 * k4 + 1]);
            }
            float p0 = hsum2(c0), p1 = hsum2(c1), p2 = hsum2(c2), p3 = hsum2(c3);
            float ownA, ownB;
            if (half == 0) {           // owns rows 0,1; exports rows 2,3
                part_s[2 * H_DIM + i] = p2;
                part_s[3 * H_DIM + i] = p3;
                ownA = p0; ownB = p1;
            } else {                   // owns rows 2,3; exports rows 0,1
                part_s[0 * H_DIM + i] = p0;
                part_s[1 * H_DIM + i] = p1;
                ownA = p2; ownB = p3;
            }
            __syncthreads();

            {
                float c  = fast_tanh(ownA + part_s[(2 * half) * H_DIM + i] + vcA);
                float u  = u_s[(2 * half) * H_DIM + i];
                float hv = hA[i];
                float hn = fmaf(u, hv - c, c);   // u*h + (1-u)*c
                if (t < lenA) hA[i] = hn;
            }
            {
                float c  = fast_tanh(ownB + part_s[(2 * half + 1) * H_DIM + i] + vcB);
                float u  = u_s[(2 * half + 1) * H_DIM + i];
                float hv = hB[i];
                float hn = fmaf(u, hv - c, c);
                if (t < lenB) hB[i] = hn;
            }
            __syncthreads();
        }

        out[s_b[2 * half]     * H_DIM + i] = hA[i];
        out[s_b[2 * half + 1] * H_DIM + i] = hB[i];
        __syncthreads();
    }
}

// ---------------------------------------------------------------------------
extern "C" void kernel_launch(void* const* d_in, const int* in_sizes, int n_in,
                              void* d_out, int out_size) {
    (void)in_sizes; (void)n_in; (void)out_size;
    const int*   item_his    = (const int*)  d_in[0];
    const int*   seq_lens    = (const int*)  d_in[1];
    const float* embedding   = (const float*)d_in[2];
    const float* gate_kernel = (const float*)d_in[3];
    const float* gate_bias   = (const float*)d_in[4];
    const float* cand_kernel = (const float*)d_in[5];
    const float* cand_bias   = (const float*)d_in[6];
    float*       out         = (float*)d_out;

    const int smem_proj = (64 * XCOLS + 64 * 64 + XCOLS) * 4;   // ~116 KB
    cudaFuncSetAttribute(proj_kernel, cudaFuncAttributeMaxDynamicSharedMemorySize, smem_proj);

    sort_kernel<<<1, 256>>>(seq_lens);
    proj_kernel<<<dim3(T_DIM / 64, B_DIM), 512, smem_proj>>>(
        item_his, seq_lens, embedding, gate_kernel, gate_bias, cand_kernel, cand_bias);
    gru_kernel<<<148, 256>>>(seq_lens, gate_kernel, cand_kernel, out);
}